// round 4
// baseline (speedup 1.0000x reference)
#include <cuda_runtime.h>
#include <math.h>

// Problem constants (from reference)
#define NNODES 50000
#define NEDGES_MAX 1700000
#define FIN 8
#define FOUT 12
#define NP 6
#define F48 (FIN * NP)      // 48 floats per node
#define NQ (F48 / 4)        // 12 float4 per node

// ---------------- device scratch (no allocations allowed) ----------------
__device__ float  g_deg[NNODES];
__device__ float  g_dinv[NNODES];
__device__ float4 g_agg[NNODES * NQ];   // aggregated, norm-weighted x (incl. self loop)

struct Params {
    float Mz[FIN][FOUT];   // Wz @ lzW[:, :FOUT]^T
    float Mh[FIN][FOUT];   // Wh @ lhW[:, :FOUT]^T
    float bz2[FOUT];       // bz @ lzW[:, :FOUT]^T + lzb
    float bh2[FOUT];       // bh @ lhW[:, :FOUT]^T + lhb
    float probs[NP];       // softmax(att)
};
__device__ Params g_p;

// ---------------- kernels ----------------

// Fold the two dense layers into 8x12 matrices; softmax(att). One tiny block.
__global__ void k_prep(const float* __restrict__ att,
                       const float* __restrict__ Wz, const float* __restrict__ bz,
                       const float* __restrict__ Wh, const float* __restrict__ bh,
                       const float* __restrict__ lzW, const float* __restrict__ lzb,
                       const float* __restrict__ lhW, const float* __restrict__ lhb) {
    int t = threadIdx.x;
    if (t < FIN * FOUT) {                       // 96 threads: fused matrices
        int f = t / FOUT, j = t % FOUT;
        float mz = 0.f, mh = 0.f;
        #pragma unroll
        for (int k = 0; k < FOUT; k++) {
            mz += Wz[f * FOUT + k] * lzW[j * (2 * FOUT) + k];
            mh += Wh[f * FOUT + k] * lhW[j * (2 * FOUT) + k];
        }
        g_p.Mz[f][j] = mz;
        g_p.Mh[f][j] = mh;
    } else if (t < FIN * FOUT + FOUT) {         // 12 threads: fused biases
        int j = t - FIN * FOUT;
        float b1 = lzb[j], b2 = lhb[j];
        #pragma unroll
        for (int k = 0; k < FOUT; k++) {
            b1 += bz[k] * lzW[j * (2 * FOUT) + k];
            b2 += bh[k] * lhW[j * (2 * FOUT) + k];
        }
        g_p.bz2[j] = b1;
        g_p.bh2[j] = b2;
    } else if (t == FIN * FOUT + FOUT) {        // 1 thread: softmax(att)
        float m = -1e30f;
        #pragma unroll
        for (int p = 0; p < NP; p++) m = fmaxf(m, att[p]);
        float e[NP], s = 0.f;
        #pragma unroll
        for (int p = 0; p < NP; p++) { e[p] = expf(att[p] - m); s += e[p]; }
        #pragma unroll
        for (int p = 0; p < NP; p++) g_p.probs[p] = e[p] / s;
    }
}

// deg = 1.0 (self loop) as initialization
__global__ void k_init_deg(int n) {
    int i = blockIdx.x * blockDim.x + threadIdx.x;
    if (i < n) g_deg[i] = 1.0f;
}

// deg[dst] += ew
__global__ void k_deg(const int* __restrict__ ei, const float* __restrict__ ew, int E) {
    int e = blockIdx.x * blockDim.x + threadIdx.x;
    if (e < E) atomicAdd(&g_deg[ei[E + e]], ew[e]);
}

// dinv = rsqrt(deg); agg init = self-loop contribution x[n] * dinv^2
// one thread per (node, quad) -> coalesced float4 traffic
__global__ void k_selfinit(const float4* __restrict__ xv, int n) {
    int i = blockIdx.x * blockDim.x + threadIdx.x;
    if (i >= n * NQ) return;
    int node = i / NQ;
    float d = g_deg[node];
    float dinv = (d > 0.f) ? rsqrtf(d) : 0.f;
    if ((i % NQ) == 0) g_dinv[node] = dinv;
    float s = dinv * dinv;
    float4 v = xv[i];
    g_agg[i] = make_float4(v.x * s, v.y * s, v.z * s, v.w * s);
}

// Main SpMM: one thread per edge, 12 independent float4 gathers + vector red.
__global__ void k_edge(const int* __restrict__ ei, const float* __restrict__ ew,
                       const float4* __restrict__ xv, int E) {
    int e = blockIdx.x * blockDim.x + threadIdx.x;
    if (e >= E) return;
    int s = ei[e];
    int d = ei[E + e];
    float w = g_dinv[s] * ew[e] * g_dinv[d];
    const float4* xs = xv + (size_t)s * NQ;
    float4* ag = g_agg + (size_t)d * NQ;
    #pragma unroll
    for (int q = 0; q < NQ; q++) {
        float4 v = __ldg(xs + q);
        asm volatile("red.global.add.v4.f32 [%0], {%1,%2,%3,%4};"
                     :: "l"(ag + q),
                        "f"(v.x * w), "f"(v.y * w), "f"(v.z * w), "f"(v.w * w)
                     : "memory");
    }
}

// Per-node epilogue: collapsed TGCN cell per period + attention sum + output head
__global__ void k_final(const float* __restrict__ linW, const float* __restrict__ linb,
                        float* __restrict__ out, int n) {
    int node = blockIdx.x * blockDim.x + threadIdx.x;
    if (node >= n) return;
    float a[F48];
    const float4* ag = g_agg + (size_t)node * NQ;
    #pragma unroll
    for (int q = 0; q < NQ; q++) {
        float4 v = ag[q];
        a[4 * q + 0] = v.x; a[4 * q + 1] = v.y; a[4 * q + 2] = v.z; a[4 * q + 3] = v.w;
    }
    float H[FOUT];
    #pragma unroll
    for (int j = 0; j < FOUT; j++) H[j] = 0.f;

    #pragma unroll
    for (int p = 0; p < NP; p++) {
        float u[FIN];
        #pragma unroll
        for (int f = 0; f < FIN; f++) u[f] = a[f * NP + p];
        float pr = g_p.probs[p];
        #pragma unroll
        for (int j = 0; j < FOUT; j++) {
            float zl = g_p.bz2[j], hl = g_p.bh2[j];
            #pragma unroll
            for (int f = 0; f < FIN; f++) {
                zl += u[f] * g_p.Mz[f][j];
                hl += u[f] * g_p.Mh[f][j];
            }
            float z  = 1.f / (1.f + expf(-zl));
            float ht = tanhf(hl);
            H[j] += pr * (1.f - z) * ht;
        }
    }
    #pragma unroll
    for (int j = 0; j < NP; j++) {
        float o = linb[j];
        #pragma unroll
        for (int f = 0; f < FOUT; f++)
            o += fmaxf(H[f], 0.f) * linW[j * FOUT + f];
        out[(size_t)node * NP + j] = o;
    }
}

// ---------------- launch ----------------
extern "C" void kernel_launch(void* const* d_in, const int* in_sizes, int n_in,
                              void* d_out, int out_size) {
    const float* x    = (const float*)d_in[0];
    const int*   ei   = (const int*)  d_in[1];
    const float* ew   = (const float*)d_in[2];
    const float* att  = (const float*)d_in[3];
    const float* Wz   = (const float*)d_in[4];
    const float* bz   = (const float*)d_in[5];
    // d_in[6], d_in[7] = Wr, br : dead (H0 = 0 makes R unused)
    const float* Wh   = (const float*)d_in[8];
    const float* bh   = (const float*)d_in[9];
    const float* lzW  = (const float*)d_in[10];
    const float* lzb  = (const float*)d_in[11];
    // d_in[12], d_in[13] = lrW, lrb : dead
    const float* lhW  = (const float*)d_in[14];
    const float* lhb  = (const float*)d_in[15];
    const float* linW = (const float*)d_in[16];
    const float* linb = (const float*)d_in[17];
    float* out = (float*)d_out;

    int E = in_sizes[2];              // edge count
    int n = in_sizes[0] / F48;        // node count

    const int B = 256;
    k_prep<<<1, 128>>>(att, Wz, bz, Wh, bh, lzW, lzb, lhW, lhb);
    k_init_deg<<<(n + B - 1) / B, B>>>(n);
    k_deg<<<(E + B - 1) / B, B>>>(ei, ew, E);
    k_selfinit<<<(n * NQ + B - 1) / B, B>>>((const float4*)x, n);
    k_edge<<<(E + B - 1) / B, B>>>(ei, ew, (const float4*)x, E);
    k_final<<<(n + B - 1) / B, B>>>(linW, linb, out, n);
}